// round 1
// baseline (speedup 1.0000x reference)
#include <cuda_runtime.h>

#define NUM_C 2048
#define LEN_Q 32
#define D 640

// Scratch (no cudaMalloc allowed): u = s_b*v_b + k_b, yg = (W u + b_fc)*gamma1
__device__ float g_u[NUM_C * D];
__device__ float g_yg[NUM_C * D];

// ---------------------------------------------------------------------------
// K1: per-batch  s_b = sum(v_b);  u_b = s_b * v_b + k_b
// ---------------------------------------------------------------------------
__global__ __launch_bounds__(256) void k_prep(const float* __restrict__ v,
                                              const float* __restrict__ k) {
    const int b = blockIdx.x;
    const float* vb = v + b * D;
    const float* kb = k + b * D;
    float* ub = g_u + b * D;

    __shared__ float red[8];
    float s = 0.f;
    for (int i = threadIdx.x; i < D; i += 256) s += vb[i];
    // warp reduce
    #pragma unroll
    for (int off = 16; off > 0; off >>= 1) s += __shfl_xor_sync(0xffffffffu, s, off);
    if ((threadIdx.x & 31) == 0) red[threadIdx.x >> 5] = s;
    __syncthreads();
    if (threadIdx.x < 32) {
        float t = (threadIdx.x < 8) ? red[threadIdx.x] : 0.f;
        #pragma unroll
        for (int off = 4; off > 0; off >>= 1) t += __shfl_xor_sync(0xffffffffu, t, off);
        if (threadIdx.x == 0) red[0] = t;
    }
    __syncthreads();
    const float sb = red[0];
    for (int i = threadIdx.x; i < D; i += 256) ub[i] = sb * vb[i] + kb[i];
}

// ---------------------------------------------------------------------------
// K2: SGEMM  yg[b,j] = (sum_d u[b,d] * W[j,d] + b_fc[j]) * gamma1[j]
// A = g_u (M=2048 x K=640, row-major), B = W (N=640 x K=640, row-major) -> NT gemm
// 64x64 tile, BK=16, 256 threads, 4x4 per thread.
// ---------------------------------------------------------------------------
__global__ __launch_bounds__(256) void k_gemm(const float* __restrict__ W,
                                              const float* __restrict__ bfc,
                                              const float* __restrict__ gamma) {
    __shared__ __align__(16) float As[16][68];  // [k][m], pad 4 -> row stride 272B (16B aligned)
    __shared__ __align__(16) float Bs[16][68];  // [k][n]

    const int bm = blockIdx.y * 64;
    const int bn = blockIdx.x * 64;
    const int tid = threadIdx.x;
    const int tx = tid & 15;   // n-tile coord
    const int ty = tid >> 4;   // m-tile coord

    float acc[4][4] = {};

    for (int k0 = 0; k0 < D; k0 += 16) {
        #pragma unroll
        for (int i = 0; i < 4; i++) {
            const int e = tid + i * 256;       // 0..1023
            const int r = e >> 4;              // 0..63 (tile row)
            const int c = e & 15;              // 0..15 (tile k)
            As[c][r] = g_u[(bm + r) * D + k0 + c];
            Bs[c][r] = W[(bn + r) * D + k0 + c];
        }
        __syncthreads();

        #pragma unroll
        for (int kk = 0; kk < 16; kk++) {
            float a[4], bv[4];
            *(float4*)a  = *(const float4*)(&As[kk][ty * 4]);
            *(float4*)bv = *(const float4*)(&Bs[kk][tx * 4]);
            #pragma unroll
            for (int i = 0; i < 4; i++)
                #pragma unroll
                for (int j = 0; j < 4; j++)
                    acc[i][j] = fmaf(a[i], bv[j], acc[i][j]);
        }
        __syncthreads();
    }

    #pragma unroll
    for (int i = 0; i < 4; i++) {
        const int row = bm + ty * 4 + i;
        #pragma unroll
        for (int j = 0; j < 4; j++) {
            const int col = bn + tx * 4 + j;
            g_yg[row * D + col] = (acc[i][j] + bfc[col]) * gamma[col];
        }
    }
}

// ---------------------------------------------------------------------------
// K3: per (b,q) row:  z = q_row + yg_b ;  out = LN(z) * ln_w + ln_b
// 1 block per batch (2048 blocks), 32 warps, warp w owns q-row w.
// D=640 -> 160 float4 per row -> 5 float4 per lane.
// ---------------------------------------------------------------------------
__global__ __launch_bounds__(1024) void k_ln(const float* __restrict__ q,
                                             const float* __restrict__ lnw,
                                             const float* __restrict__ lnb,
                                             float* __restrict__ out) {
    const int b = blockIdx.x;
    __shared__ __align__(16) float s_yg[D];
    __shared__ __align__(16) float s_w[D];
    __shared__ __align__(16) float s_b[D];

    for (int i = threadIdx.x; i < D; i += 1024) {
        s_yg[i] = g_yg[b * D + i];
        s_w[i]  = lnw[i];
        s_b[i]  = lnb[i];
    }
    __syncthreads();

    const int w    = threadIdx.x >> 5;
    const int lane = threadIdx.x & 31;
    const long row = (long)b * LEN_Q + w;
    const float4* qrow = (const float4*)(q + row * D);
    float4* orow       = (float4*)(out + row * D);

    float z[20];
    float sum = 0.f, sq = 0.f;
    #pragma unroll
    for (int j = 0; j < 5; j++) {
        const int c4 = j * 32 + lane;
        const float4 qv = qrow[c4];
        const float4 yv = *(const float4*)(s_yg + c4 * 4);
        const float z0 = qv.x + yv.x;
        const float z1 = qv.y + yv.y;
        const float z2 = qv.z + yv.z;
        const float z3 = qv.w + yv.w;
        z[j * 4 + 0] = z0; z[j * 4 + 1] = z1; z[j * 4 + 2] = z2; z[j * 4 + 3] = z3;
        sum += z0 + z1 + z2 + z3;
        sq  = fmaf(z0, z0, sq); sq = fmaf(z1, z1, sq);
        sq  = fmaf(z2, z2, sq); sq = fmaf(z3, z3, sq);
    }
    #pragma unroll
    for (int off = 16; off > 0; off >>= 1) {
        sum += __shfl_xor_sync(0xffffffffu, sum, off);
        sq  += __shfl_xor_sync(0xffffffffu, sq,  off);
    }
    const float inv_d = 1.0f / (float)D;
    const float mean = sum * inv_d;
    const float var  = sq * inv_d - mean * mean;
    const float rstd = rsqrtf(var + 1e-5f);

    #pragma unroll
    for (int j = 0; j < 5; j++) {
        const int c4 = j * 32 + lane;
        const int c  = c4 * 4;
        float4 o;
        o.x = (z[j * 4 + 0] - mean) * rstd * s_w[c + 0] + s_b[c + 0];
        o.y = (z[j * 4 + 1] - mean) * rstd * s_w[c + 1] + s_b[c + 1];
        o.z = (z[j * 4 + 2] - mean) * rstd * s_w[c + 2] + s_b[c + 2];
        o.w = (z[j * 4 + 3] - mean) * rstd * s_w[c + 3] + s_b[c + 3];
        orow[c4] = o;
    }
}

// ---------------------------------------------------------------------------
// Inputs (metadata order): 0=q 1=k 2=v 3=w_fc 4=b_fc 5=gamma1 6=ln_w 7=ln_b
// ---------------------------------------------------------------------------
extern "C" void kernel_launch(void* const* d_in, const int* in_sizes, int n_in,
                              void* d_out, int out_size) {
    const float* q     = (const float*)d_in[0];
    const float* k     = (const float*)d_in[1];
    const float* v     = (const float*)d_in[2];
    const float* w_fc  = (const float*)d_in[3];
    const float* b_fc  = (const float*)d_in[4];
    const float* gam   = (const float*)d_in[5];
    const float* ln_w  = (const float*)d_in[6];
    const float* ln_b  = (const float*)d_in[7];
    float* out = (float*)d_out;

    k_prep<<<NUM_C, 256>>>(v, k);
    k_gemm<<<dim3(D / 64, NUM_C / 64), 256>>>(w_fc, b_fc, gam);
    k_ln<<<NUM_C, 1024>>>(q, ln_w, ln_b, out);
}

// round 2
// speedup vs baseline: 1.4140x; 1.4140x over previous
#include <cuda_runtime.h>
#include <cuda_bf16.h>
#include <mma.h>

using namespace nvcuda;

#define NUM_C 2048
#define LEN_Q 32
#define D 640

// Scratch (no cudaMalloc allowed)
__device__ __nv_bfloat16 g_u_bf[NUM_C * D];   // u = s_b*v_b + k_b  (bf16)
__device__ __nv_bfloat16 g_w_bf[D * D];       // W in bf16
__device__ float         g_y[NUM_C * D];      // raw GEMM accumulators

// ---------------------------------------------------------------------------
// K0: convert W (fp32, row-major NxK = 640x640) to bf16
// ---------------------------------------------------------------------------
__global__ __launch_bounds__(256) void k_wconv(const float* __restrict__ W) {
    const int i4 = blockIdx.x * 256 + threadIdx.x;      // float4 index
    if (i4 >= (D * D) / 4) return;
    const float4 w = ((const float4*)W)[i4];
    __nv_bfloat162 p0 = __floats2bfloat162_rn(w.x, w.y);
    __nv_bfloat162 p1 = __floats2bfloat162_rn(w.z, w.w);
    uint2 pk;
    pk.x = *(unsigned*)&p0;
    pk.y = *(unsigned*)&p1;
    ((uint2*)g_w_bf)[i4] = pk;
}

// ---------------------------------------------------------------------------
// K1: per-batch  s_b = sum(v_b);  u_b = bf16(s_b * v_b + k_b)
// 160 threads (= D/4), one float4 per thread, v kept in registers.
// ---------------------------------------------------------------------------
__global__ __launch_bounds__(160) void k_prep(const float* __restrict__ v,
                                              const float* __restrict__ k) {
    const int b = blockIdx.x;
    const int t = threadIdx.x;
    const float4 v4 = ((const float4*)(v + b * D))[t];
    const float4 k4 = ((const float4*)(k + b * D))[t];

    __shared__ float red[5];
    float s = v4.x + v4.y + v4.z + v4.w;
    #pragma unroll
    for (int off = 16; off > 0; off >>= 1) s += __shfl_xor_sync(0xffffffffu, s, off);
    if ((t & 31) == 0) red[t >> 5] = s;
    __syncthreads();
    const float sb = red[0] + red[1] + red[2] + red[3] + red[4];

    __nv_bfloat162 p0 = __floats2bfloat162_rn(fmaf(sb, v4.x, k4.x), fmaf(sb, v4.y, k4.y));
    __nv_bfloat162 p1 = __floats2bfloat162_rn(fmaf(sb, v4.z, k4.z), fmaf(sb, v4.w, k4.w));
    uint2 pk;
    pk.x = *(unsigned*)&p0;
    pk.y = *(unsigned*)&p1;
    ((uint2*)(g_u_bf + b * D))[t] = pk;
}

// ---------------------------------------------------------------------------
// K2: bf16 tensor-core GEMM  y[b,j] = sum_d u[b,d] * W[j,d]
// A = g_u_bf (2048x640 row-major), B = W^T (col_major view of g_w_bf, ld=D).
// Block: 128 threads (4 warps), 64x64 tile; warp = 32x32 (2x2 wmma 16x16x16).
// Fragments loaded straight from global (W is L2-resident: 800 KB).
// ---------------------------------------------------------------------------
__global__ __launch_bounds__(128) void k_gemm() {
    const int bm = blockIdx.y * 64;
    const int bn = blockIdx.x * 64;
    const int w  = threadIdx.x >> 5;
    const int wm = bm + (w >> 1) * 32;   // warp row base
    const int wn = bn + (w & 1) * 32;    // warp col base

    wmma::fragment<wmma::accumulator, 16, 16, 16, float> acc[2][2];
    #pragma unroll
    for (int i = 0; i < 2; i++)
        #pragma unroll
        for (int j = 0; j < 2; j++)
            wmma::fill_fragment(acc[i][j], 0.0f);

    for (int k0 = 0; k0 < D; k0 += 16) {
        wmma::fragment<wmma::matrix_a, 16, 16, 16, __nv_bfloat16, wmma::row_major> a[2];
        wmma::fragment<wmma::matrix_b, 16, 16, 16, __nv_bfloat16, wmma::col_major> bf[2];
        #pragma unroll
        for (int i = 0; i < 2; i++)
            wmma::load_matrix_sync(a[i], g_u_bf + (wm + i * 16) * D + k0, D);
        #pragma unroll
        for (int j = 0; j < 2; j++)
            wmma::load_matrix_sync(bf[j], g_w_bf + (wn + j * 16) * D + k0, D);
        #pragma unroll
        for (int i = 0; i < 2; i++)
            #pragma unroll
            for (int j = 0; j < 2; j++)
                wmma::mma_sync(acc[i][j], a[i], bf[j], acc[i][j]);
    }

    #pragma unroll
    for (int i = 0; i < 2; i++)
        #pragma unroll
        for (int j = 0; j < 2; j++)
            wmma::store_matrix_sync(g_y + (wm + i * 16) * D + (wn + j * 16),
                                    acc[i][j], D, wmma::mem_row_major);
}

// ---------------------------------------------------------------------------
// K3: per (b,q) row:  yg = (y + b_fc)*gamma1 ;  z = q_row + yg ;
//     out = LN(z) * ln_w + ln_b
// 1 block per batch, 32 warps, warp w owns q-row w.
// ---------------------------------------------------------------------------
__global__ __launch_bounds__(1024) void k_ln(const float* __restrict__ q,
                                             const float* __restrict__ bfc,
                                             const float* __restrict__ gam,
                                             const float* __restrict__ lnw,
                                             const float* __restrict__ lnb,
                                             float* __restrict__ out) {
    const int b = blockIdx.x;
    __shared__ __align__(16) float s_yg[D];
    __shared__ __align__(16) float s_w[D];
    __shared__ __align__(16) float s_b[D];

    for (int i = threadIdx.x; i < D; i += 1024) {
        s_yg[i] = (g_y[b * D + i] + bfc[i]) * gam[i];
        s_w[i]  = lnw[i];
        s_b[i]  = lnb[i];
    }
    __syncthreads();

    const int w    = threadIdx.x >> 5;
    const int lane = threadIdx.x & 31;
    const long row = (long)b * LEN_Q + w;
    const float4* qrow = (const float4*)(q + row * D);
    float4* orow       = (float4*)(out + row * D);

    float z[20];
    float sum = 0.f, sq = 0.f;
    #pragma unroll
    for (int j = 0; j < 5; j++) {
        const int c4 = j * 32 + lane;
        const float4 qv = qrow[c4];
        const float4 yv = *(const float4*)(s_yg + c4 * 4);
        const float z0 = qv.x + yv.x;
        const float z1 = qv.y + yv.y;
        const float z2 = qv.z + yv.z;
        const float z3 = qv.w + yv.w;
        z[j * 4 + 0] = z0; z[j * 4 + 1] = z1; z[j * 4 + 2] = z2; z[j * 4 + 3] = z3;
        sum += z0 + z1 + z2 + z3;
        sq  = fmaf(z0, z0, sq); sq = fmaf(z1, z1, sq);
        sq  = fmaf(z2, z2, sq); sq = fmaf(z3, z3, sq);
    }
    #pragma unroll
    for (int off = 16; off > 0; off >>= 1) {
        sum += __shfl_xor_sync(0xffffffffu, sum, off);
        sq  += __shfl_xor_sync(0xffffffffu, sq,  off);
    }
    const float inv_d = 1.0f / (float)D;
    const float mean = sum * inv_d;
    const float var  = sq * inv_d - mean * mean;
    const float rstd = rsqrtf(var + 1e-5f);

    #pragma unroll
    for (int j = 0; j < 5; j++) {
        const int c4 = j * 32 + lane;
        const int c  = c4 * 4;
        float4 o;
        o.x = (z[j * 4 + 0] - mean) * rstd * s_w[c + 0] + s_b[c + 0];
        o.y = (z[j * 4 + 1] - mean) * rstd * s_w[c + 1] + s_b[c + 1];
        o.z = (z[j * 4 + 2] - mean) * rstd * s_w[c + 2] + s_b[c + 2];
        o.w = (z[j * 4 + 3] - mean) * rstd * s_w[c + 3] + s_b[c + 3];
        orow[c4] = o;
    }
}

// ---------------------------------------------------------------------------
// Inputs: 0=q 1=k 2=v 3=w_fc 4=b_fc 5=gamma1 6=ln_w 7=ln_b
// ---------------------------------------------------------------------------
extern "C" void kernel_launch(void* const* d_in, const int* in_sizes, int n_in,
                              void* d_out, int out_size) {
    const float* q     = (const float*)d_in[0];
    const float* k     = (const float*)d_in[1];
    const float* v     = (const float*)d_in[2];
    const float* w_fc  = (const float*)d_in[3];
    const float* b_fc  = (const float*)d_in[4];
    const float* gam   = (const float*)d_in[5];
    const float* ln_w  = (const float*)d_in[6];
    const float* ln_b  = (const float*)d_in[7];
    float* out = (float*)d_out;

    k_wconv<<<(D * D / 4 + 255) / 256, 256>>>(w_fc);
    k_prep<<<NUM_C, 160>>>(v, k);
    k_gemm<<<dim3(D / 64, NUM_C / 64), 128>>>();
    k_ln<<<NUM_C, 1024>>>(q, b_fc, gam, ln_w, ln_b, out);
}

// round 3
// speedup vs baseline: 1.8244x; 1.2902x over previous
#include <cuda_runtime.h>
#include <cuda_bf16.h>
#include <mma.h>

using namespace nvcuda;

#define NUM_C 2048
#define LEN_Q 32
#define D 640

// Scratch (no cudaMalloc allowed)
__device__ __nv_bfloat16 g_u_bf[NUM_C * D];   // u = s_b*v_b + k_b  (bf16)
__device__ __nv_bfloat16 g_w_bf[D * D];       // W in bf16
__device__ __nv_bfloat16 g_yg[NUM_C * D];     // yg = (W u + b_fc)*gamma1 (bf16)

#define WCONV_BLOCKS 400   // (640*640/4)/256

// ---------------------------------------------------------------------------
// K1: fused  [blocks 0..399]  W fp32 -> bf16
//            [blocks 400..2447] per-batch s_b = sum(v_b); u_b = bf16(s_b*v_b + k_b)
// ---------------------------------------------------------------------------
__global__ __launch_bounds__(256) void k_prep(const float* __restrict__ W,
                                              const float* __restrict__ v,
                                              const float* __restrict__ k) {
    const int t = threadIdx.x;
    if (blockIdx.x < WCONV_BLOCKS) {
        const int i4 = blockIdx.x * 256 + t;
        const float4 w = ((const float4*)W)[i4];
        __nv_bfloat162 p0 = __floats2bfloat162_rn(w.x, w.y);
        __nv_bfloat162 p1 = __floats2bfloat162_rn(w.z, w.w);
        uint2 pk; pk.x = *(unsigned*)&p0; pk.y = *(unsigned*)&p1;
        ((uint2*)g_w_bf)[i4] = pk;
        return;
    }
    const int b = blockIdx.x - WCONV_BLOCKS;
    __shared__ float red[5];
    float4 v4, k4;
    if (t < 160) {
        v4 = ((const float4*)(v + b * D))[t];
        k4 = ((const float4*)(k + b * D))[t];
        float s = v4.x + v4.y + v4.z + v4.w;
        #pragma unroll
        for (int off = 16; off > 0; off >>= 1) s += __shfl_xor_sync(0xffffffffu, s, off);
        if ((t & 31) == 0) red[t >> 5] = s;
    }
    __syncthreads();
    if (t < 160) {
        const float sb = red[0] + red[1] + red[2] + red[3] + red[4];
        __nv_bfloat162 p0 = __floats2bfloat162_rn(fmaf(sb, v4.x, k4.x), fmaf(sb, v4.y, k4.y));
        __nv_bfloat162 p1 = __floats2bfloat162_rn(fmaf(sb, v4.z, k4.z), fmaf(sb, v4.w, k4.w));
        uint2 pk; pk.x = *(unsigned*)&p0; pk.y = *(unsigned*)&p1;
        ((uint2*)(g_u_bf + b * D))[t] = pk;
    }
}

// ---------------------------------------------------------------------------
// K2: bf16 wmma GEMM, smem-staged.  yg[b,j] = (sum_d u[b,d]*W[j,d] + bfc[j])*gam[j]
// Tile 64x64, BK=64, 128 threads (4 warps, each 32x32). Grid 10 x 32 = 320
// blocks -> single wave. Epilogue through smem, bf16 output.
// ---------------------------------------------------------------------------
#define GK_PAD 72   // 64 + 8 bf16 pad (row stride 144B)

__global__ __launch_bounds__(128) void k_gemm(const float* __restrict__ bfc,
                                              const float* __restrict__ gam) {
    __shared__ __align__(16) unsigned char smem_raw[2 * 64 * GK_PAD * 2];
    __nv_bfloat16* As = (__nv_bfloat16*)smem_raw;            // [64][72]
    __nv_bfloat16* Bs = As + 64 * GK_PAD;                    // [64][72]
    float* Sout = (float*)smem_raw;                          // [64][64] (epilogue alias)

    const int bm = blockIdx.y * 64;
    const int bn = blockIdx.x * 64;
    const int tid = threadIdx.x;
    const int w  = tid >> 5;
    const int wm_l = (w >> 1) * 32;
    const int wn_l = (w & 1) * 32;

    wmma::fragment<wmma::accumulator, 16, 16, 16, float> acc[2][2];
    #pragma unroll
    for (int i = 0; i < 2; i++)
        #pragma unroll
        for (int j = 0; j < 2; j++) wmma::fill_fragment(acc[i][j], 0.0f);

    for (int k0 = 0; k0 < D; k0 += 64) {
        #pragma unroll
        for (int i = 0; i < 4; i++) {
            const int e = tid + i * 128;       // 0..511
            const int r  = e >> 3;             // 0..63
            const int c8 = e & 7;              // 0..7 (uint4 = 8 bf16)
            *(uint4*)&As[r * GK_PAD + c8 * 8] =
                *(const uint4*)&g_u_bf[(bm + r) * D + k0 + c8 * 8];
            *(uint4*)&Bs[r * GK_PAD + c8 * 8] =
                *(const uint4*)&g_w_bf[(bn + r) * D + k0 + c8 * 8];
        }
        __syncthreads();

        #pragma unroll
        for (int kk = 0; kk < 4; kk++) {
            wmma::fragment<wmma::matrix_a, 16, 16, 16, __nv_bfloat16, wmma::row_major> a[2];
            wmma::fragment<wmma::matrix_b, 16, 16, 16, __nv_bfloat16, wmma::col_major> bb[2];
            #pragma unroll
            for (int i = 0; i < 2; i++)
                wmma::load_matrix_sync(a[i], &As[(wm_l + i * 16) * GK_PAD + kk * 16], GK_PAD);
            #pragma unroll
            for (int j = 0; j < 2; j++)
                wmma::load_matrix_sync(bb[j], &Bs[(wn_l + j * 16) * GK_PAD + kk * 16], GK_PAD);
            #pragma unroll
            for (int i = 0; i < 2; i++)
                #pragma unroll
                for (int j = 0; j < 2; j++)
                    wmma::mma_sync(acc[i][j], a[i], bb[j], acc[i][j]);
        }
        __syncthreads();
    }

    // epilogue: acc -> smem -> (x+b)*gamma -> bf16 global
    #pragma unroll
    for (int i = 0; i < 2; i++)
        #pragma unroll
        for (int j = 0; j < 2; j++)
            wmma::store_matrix_sync(&Sout[(wm_l + i * 16) * 64 + wn_l + j * 16],
                                    acc[i][j], 64, wmma::mem_row_major);
    __syncthreads();

    #pragma unroll
    for (int i = 0; i < 16; i++) {
        const int e   = tid + i * 128;     // 0..2047  (bf162 units)
        const int r   = e >> 5;            // 0..63
        const int cp  = e & 31;            // 0..31
        const int col = bn + cp * 2;
        const float x0 = (Sout[r * 64 + cp * 2 + 0] + bfc[col + 0]) * gam[col + 0];
        const float x1 = (Sout[r * 64 + cp * 2 + 1] + bfc[col + 1]) * gam[col + 1];
        *(__nv_bfloat162*)&g_yg[(bm + r) * D + col] = __floats2bfloat162_rn(x0, x1);
    }
}

// ---------------------------------------------------------------------------
// K3: per (b,q) row:  z = q_row + yg_b ;  out = LN(z)*ln_w + ln_b
// 512 threads = 16 warps = 8 rows (2 warps per row, float2 units).
// grid = 2048*4. Streaming hints on q/out.
// ---------------------------------------------------------------------------
__global__ __launch_bounds__(512) void k_ln(const float* __restrict__ q,
                                            const float* __restrict__ lnw,
                                            const float* __restrict__ lnb,
                                            float* __restrict__ out) {
    const int b       = blockIdx.x >> 2;
    const int rowbase = (blockIdx.x & 3) * 8;

    __shared__ __align__(8) float s_yg[D];
    __shared__ __align__(8) float s_w[D];
    __shared__ __align__(8) float s_b[D];
    __shared__ float2 s_part[16];

    for (int i = threadIdx.x; i < D; i += 512) {
        s_yg[i] = __bfloat162float(g_yg[b * D + i]);
        s_w[i]  = lnw[i];
        s_b[i]  = lnb[i];
    }
    __syncthreads();

    const int pair   = threadIdx.x >> 6;       // 0..7 : row within group
    const int lane64 = threadIdx.x & 63;       // 0..63
    const int warpid = threadIdx.x >> 5;       // 0..15
    const long row   = (long)b * LEN_Q + rowbase + pair;
    const float2* qrow = (const float2*)(q + row * D);
    float2* orow       = (float2*)(out + row * D);

    float2 z[5];
    float sum = 0.f, sq = 0.f;
    #pragma unroll
    for (int j = 0; j < 5; j++) {
        const int c2 = j * 64 + lane64;        // 0..319
        const float2 qv = __ldcs(&qrow[c2]);
        const float2 yv = *(const float2*)(s_yg + c2 * 2);
        const float z0 = qv.x + yv.x;
        const float z1 = qv.y + yv.y;
        z[j].x = z0; z[j].y = z1;
        sum += z0 + z1;
        sq = fmaf(z0, z0, sq); sq = fmaf(z1, z1, sq);
    }
    #pragma unroll
    for (int off = 16; off > 0; off >>= 1) {
        sum += __shfl_xor_sync(0xffffffffu, sum, off);
        sq  += __shfl_xor_sync(0xffffffffu, sq,  off);
    }
    if ((threadIdx.x & 31) == 0) s_part[warpid] = make_float2(sum, sq);
    __syncthreads();
    {
        const float2 p0 = s_part[pair * 2 + 0];
        const float2 p1 = s_part[pair * 2 + 1];
        sum = p0.x + p1.x;
        sq  = p0.y + p1.y;
    }
    const float inv_d = 1.0f / (float)D;
    const float mean = sum * inv_d;
    const float var  = sq * inv_d - mean * mean;
    const float rstd = rsqrtf(var + 1e-5f);

    #pragma unroll
    for (int j = 0; j < 5; j++) {
        const int c2 = j * 64 + lane64;
        const int c  = c2 * 2;
        float2 o;
        o.x = (z[j].x - mean) * rstd * s_w[c + 0] + s_b[c + 0];
        o.y = (z[j].y - mean) * rstd * s_w[c + 1] + s_b[c + 1];
        __stcs(&orow[c2], o);
    }
}

// ---------------------------------------------------------------------------
// Inputs: 0=q 1=k 2=v 3=w_fc 4=b_fc 5=gamma1 6=ln_w 7=ln_b
// ---------------------------------------------------------------------------
extern "C" void kernel_launch(void* const* d_in, const int* in_sizes, int n_in,
                              void* d_out, int out_size) {
    const float* q     = (const float*)d_in[0];
    const float* k     = (const float*)d_in[1];
    const float* v     = (const float*)d_in[2];
    const float* w_fc  = (const float*)d_in[3];
    const float* b_fc  = (const float*)d_in[4];
    const float* gam   = (const float*)d_in[5];
    const float* ln_w  = (const float*)d_in[6];
    const float* ln_b  = (const float*)d_in[7];
    float* out = (float*)d_out;

    k_prep<<<WCONV_BLOCKS + NUM_C, 256>>>(w_fc, v, k);
    k_gemm<<<dim3(D / 64, NUM_C / 64), 128>>>(b_fc, gam);
    k_ln<<<NUM_C * 4, 512>>>(q, ln_w, ln_b, out);
}

// round 4
// speedup vs baseline: 1.9145x; 1.0494x over previous
#include <cuda_runtime.h>
#include <cuda_bf16.h>
#include <mma.h>

using namespace nvcuda;

#define NUM_C 2048
#define LEN_Q 32
#define D 640

// Scratch (no cudaMalloc allowed)
__device__ __nv_bfloat16 g_u_bf[NUM_C * D];   // u = s_b*v_b + k_b  (bf16)
__device__ __nv_bfloat16 g_w_bf[D * D];       // W in bf16
__device__ __nv_bfloat16 g_yg[NUM_C * D];     // yg = (W u + b_fc)*gamma1 (bf16)

#define WCONV_BLOCKS 400   // (640*640/4)/256
#define PREP_BLOCKS  256   // 2048 batches / 8 per block

// ---------------------------------------------------------------------------
// K1: fused  [blocks 0..399]   W fp32 -> bf16
//            [blocks 400..655] u prep, warp-per-batch (8 batches/block)
// ---------------------------------------------------------------------------
__global__ __launch_bounds__(256) void k_prep(const float* __restrict__ W,
                                              const float* __restrict__ v,
                                              const float* __restrict__ k) {
    const int t = threadIdx.x;
    if (blockIdx.x < WCONV_BLOCKS) {
        const int i4 = blockIdx.x * 256 + t;
        const float4 w = ((const float4*)W)[i4];
        __nv_bfloat162 p0 = __floats2bfloat162_rn(w.x, w.y);
        __nv_bfloat162 p1 = __floats2bfloat162_rn(w.z, w.w);
        uint2 pk; pk.x = *(unsigned*)&p0; pk.y = *(unsigned*)&p1;
        ((uint2*)g_w_bf)[i4] = pk;
        return;
    }
    const int b    = (blockIdx.x - WCONV_BLOCKS) * 8 + (t >> 5);
    const int lane = t & 31;
    const float4* vp = (const float4*)(v + b * D);
    const float4* kp = (const float4*)(k + b * D);

    float4 vv[5], kk[5];
    float s = 0.f;
    #pragma unroll
    for (int j = 0; j < 5; j++) {
        vv[j] = vp[lane + j * 32];
        kk[j] = kp[lane + j * 32];
        s += vv[j].x + vv[j].y + vv[j].z + vv[j].w;
    }
    #pragma unroll
    for (int off = 16; off > 0; off >>= 1) s += __shfl_xor_sync(0xffffffffu, s, off);

    uint2* up = (uint2*)(g_u_bf + b * D);
    #pragma unroll
    for (int j = 0; j < 5; j++) {
        __nv_bfloat162 p0 = __floats2bfloat162_rn(fmaf(s, vv[j].x, kk[j].x),
                                                  fmaf(s, vv[j].y, kk[j].y));
        __nv_bfloat162 p1 = __floats2bfloat162_rn(fmaf(s, vv[j].z, kk[j].z),
                                                  fmaf(s, vv[j].w, kk[j].w));
        uint2 pk; pk.x = *(unsigned*)&p0; pk.y = *(unsigned*)&p1;
        up[lane + j * 32] = pk;
    }
}

// ---------------------------------------------------------------------------
// K2: bf16 wmma GEMM, cp.async double-buffered.
// yg[b,j] = (sum_d u[b,d]*W[j,d] + bfc[j])*gam[j], bf16 output.
// Tile 64x64, BK=64, 2 stages, 128 threads (4 warps, each 32x32).
// ---------------------------------------------------------------------------
#define GK_PAD 72   // 64 + 8 bf16 pad

__device__ __forceinline__ void cp_async16(void* smem_dst, const void* gmem_src) {
    unsigned s = (unsigned)__cvta_generic_to_shared(smem_dst);
    asm volatile("cp.async.ca.shared.global [%0], [%1], 16;\n" :: "r"(s), "l"(gmem_src));
}
__device__ __forceinline__ void cp_commit() {
    asm volatile("cp.async.commit_group;\n");
}

__global__ __launch_bounds__(128) void k_gemm(const float* __restrict__ bfc,
                                              const float* __restrict__ gam) {
    __shared__ __align__(16) __nv_bfloat16 As[2][64 * GK_PAD];
    __shared__ __align__(16) __nv_bfloat16 Bs[2][64 * GK_PAD];
    __shared__ __align__(16) float Sout[64 * 64];

    const int bm = blockIdx.y * 64;
    const int bn = blockIdx.x * 64;
    const int tid = threadIdx.x;
    const int w  = tid >> 5;
    const int wm_l = (w >> 1) * 32;
    const int wn_l = (w & 1) * 32;

    // per-thread load coords (4 x 16B for A, 4 for B per stage)
    const int lr[4]  = { (tid + 0)   >> 3, (tid + 128) >> 3,
                         (tid + 256) >> 3, (tid + 384) >> 3 };
    const int lc8[4] = { (tid & 7) * 8, (tid & 7) * 8, (tid & 7) * 8, (tid & 7) * 8 };

    auto prefetch = [&](int st, int k0) {
        #pragma unroll
        for (int i = 0; i < 4; i++) {
            cp_async16(&As[st][lr[i] * GK_PAD + lc8[i]],
                       &g_u_bf[(bm + lr[i]) * D + k0 + lc8[i]]);
            cp_async16(&Bs[st][lr[i] * GK_PAD + lc8[i]],
                       &g_w_bf[(bn + lr[i]) * D + k0 + lc8[i]]);
        }
        cp_commit();
    };

    wmma::fragment<wmma::accumulator, 16, 16, 16, float> acc[2][2];
    #pragma unroll
    for (int i = 0; i < 2; i++)
        #pragma unroll
        for (int j = 0; j < 2; j++) wmma::fill_fragment(acc[i][j], 0.0f);

    prefetch(0, 0);

    #pragma unroll 1
    for (int kt = 0; kt < 10; kt++) {
        if (kt + 1 < 10) {
            prefetch((kt + 1) & 1, (kt + 1) * 64);
            asm volatile("cp.async.wait_group 1;\n");
        } else {
            asm volatile("cp.async.wait_group 0;\n");
        }
        __syncthreads();

        const int st = kt & 1;
        #pragma unroll
        for (int kk = 0; kk < 4; kk++) {
            wmma::fragment<wmma::matrix_a, 16, 16, 16, __nv_bfloat16, wmma::row_major> a[2];
            wmma::fragment<wmma::matrix_b, 16, 16, 16, __nv_bfloat16, wmma::col_major> bb[2];
            #pragma unroll
            for (int i = 0; i < 2; i++)
                wmma::load_matrix_sync(a[i], &As[st][(wm_l + i * 16) * GK_PAD + kk * 16], GK_PAD);
            #pragma unroll
            for (int j = 0; j < 2; j++)
                wmma::load_matrix_sync(bb[j], &Bs[st][(wn_l + j * 16) * GK_PAD + kk * 16], GK_PAD);
            #pragma unroll
            for (int i = 0; i < 2; i++)
                #pragma unroll
                for (int j = 0; j < 2; j++)
                    wmma::mma_sync(acc[i][j], a[i], bb[j], acc[i][j]);
        }
        __syncthreads();
    }

    #pragma unroll
    for (int i = 0; i < 2; i++)
        #pragma unroll
        for (int j = 0; j < 2; j++)
            wmma::store_matrix_sync(&Sout[(wm_l + i * 16) * 64 + wn_l + j * 16],
                                    acc[i][j], 64, wmma::mem_row_major);
    __syncthreads();

    #pragma unroll
    for (int i = 0; i < 16; i++) {
        const int e   = tid + i * 128;     // 0..2047  (bf162 units)
        const int r   = e >> 5;
        const int cp  = e & 31;
        const int col = bn + cp * 2;
        const float x0 = (Sout[r * 64 + cp * 2 + 0] + __ldg(&bfc[col + 0])) * __ldg(&gam[col + 0]);
        const float x1 = (Sout[r * 64 + cp * 2 + 1] + __ldg(&bfc[col + 1])) * __ldg(&gam[col + 1]);
        *(__nv_bfloat162*)&g_yg[(bm + r) * D + col] = __floats2bfloat162_rn(x0, x1);
    }
}

// ---------------------------------------------------------------------------
// K3: per (b,q) row:  z = q_row + yg_b ;  out = LN(z)*ln_w + ln_b
// 512 threads = 16 warps = 8 rows (2 warps per row, float2 units).
// grid = 2048*4. Streaming hints on q/out.
// ---------------------------------------------------------------------------
__global__ __launch_bounds__(512) void k_ln(const float* __restrict__ q,
                                            const float* __restrict__ lnw,
                                            const float* __restrict__ lnb,
                                            float* __restrict__ out) {
    const int b       = blockIdx.x >> 2;
    const int rowbase = (blockIdx.x & 3) * 8;

    __shared__ __align__(8) float s_yg[D];
    __shared__ __align__(8) float s_w[D];
    __shared__ __align__(8) float s_b[D];
    __shared__ float2 s_part[16];

    for (int i = threadIdx.x; i < D; i += 512) {
        s_yg[i] = __bfloat162float(g_yg[b * D + i]);
        s_w[i]  = lnw[i];
        s_b[i]  = lnb[i];
    }
    __syncthreads();

    const int pair   = threadIdx.x >> 6;       // 0..7 : row within group
    const int lane64 = threadIdx.x & 63;       // 0..63
    const int warpid = threadIdx.x >> 5;       // 0..15
    const long row   = (long)b * LEN_Q + rowbase + pair;
    const float2* qrow = (const float2*)(q + row * D);
    float2* orow       = (float2*)(out + row * D);

    float2 z[5];
    float sum = 0.f, sq = 0.f;
    #pragma unroll
    for (int j = 0; j < 5; j++) {
        const int c2 = j * 64 + lane64;        // 0..319
        const float2 qv = __ldcs(&qrow[c2]);
        const float2 yv = *(const float2*)(s_yg + c2 * 2);
        const float z0 = qv.x + yv.x;
        const float z1 = qv.y + yv.y;
        z[j].x = z0; z[j].y = z1;
        sum += z0 + z1;
        sq = fmaf(z0, z0, sq); sq = fmaf(z1, z1, sq);
    }
    #pragma unroll
    for (int off = 16; off > 0; off >>= 1) {
        sum += __shfl_xor_sync(0xffffffffu, sum, off);
        sq  += __shfl_xor_sync(0xffffffffu, sq,  off);
    }
    if ((threadIdx.x & 31) == 0) s_part[warpid] = make_float2(sum, sq);
    __syncthreads();
    {
        const float2 p0 = s_part[pair * 2 + 0];
        const float2 p1 = s_part[pair * 2 + 1];
        sum = p0.x + p1.x;
        sq  = p0.y + p1.y;
    }
    const float inv_d = 1.0f / (float)D;
    const float mean = sum * inv_d;
    const float var  = sq * inv_d - mean * mean;
    const float rstd = rsqrtf(var + 1e-5f);

    #pragma unroll
    for (int j = 0; j < 5; j++) {
        const int c2 = j * 64 + lane64;
        const int c  = c2 * 2;
        float2 o;
        o.x = (z[j].x - mean) * rstd * s_w[c + 0] + s_b[c + 0];
        o.y = (z[j].y - mean) * rstd * s_w[c + 1] + s_b[c + 1];
        __stcs(&orow[c2], o);
    }
}

// ---------------------------------------------------------------------------
// Inputs: 0=q 1=k 2=v 3=w_fc 4=b_fc 5=gamma1 6=ln_w 7=ln_b
// ---------------------------------------------------------------------------
extern "C" void kernel_launch(void* const* d_in, const int* in_sizes, int n_in,
                              void* d_out, int out_size) {
    const float* q     = (const float*)d_in[0];
    const float* k     = (const float*)d_in[1];
    const float* v     = (const float*)d_in[2];
    const float* w_fc  = (const float*)d_in[3];
    const float* b_fc  = (const float*)d_in[4];
    const float* gam   = (const float*)d_in[5];
    const float* ln_w  = (const float*)d_in[6];
    const float* ln_b  = (const float*)d_in[7];
    float* out = (float*)d_out;

    k_prep<<<WCONV_BLOCKS + PREP_BLOCKS, 256>>>(w_fc, v, k);
    k_gemm<<<dim3(D / 64, NUM_C / 64), 128>>>(b_fc, gam);
    k_ln<<<NUM_C * 4, 512>>>(q, ln_w, ln_b, out);
}